// round 1
// baseline (speedup 1.0000x reference)
#include <cuda_runtime.h>
#include <cfloat>
#include <climits>

// ---------------- problem constants ----------------
#define BB   16
#define TT   1024
#define FEAT 768
#define HH   256
#define CC   50
#define LL   2
#define W1   128
#define GG   32
#define KK   3
#define BT   (BB*TT)        // 16384
#define BTK  (BT*KK)        // 49152

// ---------------- scratch (device globals; no allocs allowed) ----------------
__device__ float g_hA[BT*HH];
__device__ float g_hB[BT*HH];
__device__ float g_t1[BT*W1];
__device__ float g_t2[BT*W1];
__device__ float g_t3[BT*HH];
__device__ float g_xx[BT];
__device__ int   g_idx[BT*KK];
__device__ float g_inner[BB*TT*TT];   // 64 MB
__device__ float g_f[BTK*2*HH];       // 96 MB
__device__ float g_s1[BTK*W1];
__device__ float g_s2[BTK*W1];
__device__ float g_s3[BTK*HH];

// ---------------- generic SGEMM: C = act(A[M,K] @ W[N,K]^T + bias) ----------------
// 128x128 block tile, 8-deep K tile, 256 threads, 8x8 per-thread microtile.
// M must be a multiple of 128 and K a multiple of 8 (true for all call sites);
// N is bounds-checked (needed for N=50).
template<bool RELU, bool HAS_BIAS>
__global__ void __launch_bounds__(256)
sgemm_nt_kernel(const float* __restrict__ A, const float* __restrict__ Bw,
                const float* __restrict__ bias, float* __restrict__ C,
                int M, int N, int Kd,
                long long strideA, long long strideB, long long strideC)
{
    const int batch = blockIdx.z;
    A  += (long long)batch * strideA;
    Bw += (long long)batch * strideB;
    C  += (long long)batch * strideC;

    __shared__ float As[8][132];
    __shared__ float Bs[8][132];

    const int tid = threadIdx.x;
    const int m0 = blockIdx.y * 128;
    const int n0 = blockIdx.x * 128;

    const int lrow = tid >> 1;          // 0..127
    const int lcol = (tid & 1) * 4;     // 0 or 4

    const int tx = tid & 15;            // n direction
    const int ty = tid >> 4;            // m direction

    float acc[8][8];
#pragma unroll
    for (int i = 0; i < 8; i++)
#pragma unroll
        for (int j = 0; j < 8; j++) acc[i][j] = 0.f;

    const float* Aptr = A + (long long)(m0 + lrow) * Kd + lcol;
    const bool bvalid = (n0 + lrow) < N;
    const float* Bptr = Bw + (long long)(bvalid ? (n0 + lrow) : 0) * Kd + lcol;

    for (int kt = 0; kt < Kd; kt += 8) {
        float4 av = *(const float4*)(Aptr + kt);
        float4 bv = bvalid ? *(const float4*)(Bptr + kt) : make_float4(0.f,0.f,0.f,0.f);
        As[lcol+0][lrow] = av.x; As[lcol+1][lrow] = av.y;
        As[lcol+2][lrow] = av.z; As[lcol+3][lrow] = av.w;
        Bs[lcol+0][lrow] = bv.x; Bs[lcol+1][lrow] = bv.y;
        Bs[lcol+2][lrow] = bv.z; Bs[lcol+3][lrow] = bv.w;
        __syncthreads();
#pragma unroll
        for (int k = 0; k < 8; k++) {
            float a[8], b[8];
#pragma unroll
            for (int i = 0; i < 4; i++) {
                a[i]   = As[k][ty*4 + i];
                a[4+i] = As[k][64 + ty*4 + i];
            }
#pragma unroll
            for (int j = 0; j < 4; j++) {
                b[j]   = Bs[k][tx*4 + j];
                b[4+j] = Bs[k][64 + tx*4 + j];
            }
#pragma unroll
            for (int i = 0; i < 8; i++)
#pragma unroll
                for (int j = 0; j < 8; j++)
                    acc[i][j] += a[i] * b[j];
        }
        __syncthreads();
    }

#pragma unroll
    for (int i = 0; i < 8; i++) {
        const int m = m0 + ((i < 4) ? (ty*4 + i) : (64 + ty*4 + i - 4));
        float* Crow = C + (long long)m * N;
#pragma unroll
        for (int j = 0; j < 8; j++) {
            const int n = n0 + ((j < 4) ? (tx*4 + j) : (64 + tx*4 + j - 4));
            if (n < N) {
                float v = acc[i][j];
                if (HAS_BIAS) v += bias[n];
                if (RELU) v = fmaxf(v, 0.f);
                Crow[n] = v;
            }
        }
    }
}

// ---------------- backbone grouped conv1d (groups=4, cin/g=64, k=3, pad=1) + relu ----
__global__ void __launch_bounds__(256)
conv_backbone_kernel(const float* __restrict__ x, const float* __restrict__ w,
                     const float* __restrict__ bias, float* __restrict__ y)
{
    const int b = blockIdx.x >> 7;
    const int tbase = (blockIdx.x & 127) << 3;   // 8 t positions per block
    __shared__ float hs[10][HH];
    const int tid = threadIdx.x;                 // = output channel c
#pragma unroll
    for (int r = 0; r < 10; r++) {
        const int t = tbase - 1 + r;
        hs[r][tid] = (t >= 0 && t < TT) ? x[((long long)(b*TT + t))*HH + tid] : 0.f;
    }
    __syncthreads();
    const int c = tid;
    const int g = c >> 6;
    const float* wc = w + c * 192;               // [64][3]
    float acc[8];
    const float bb = bias[c];
#pragma unroll
    for (int t = 0; t < 8; t++) acc[t] = bb;
    for (int i = 0; i < 64; i++) {
        const int base = g*64 + i;
        const float w0 = wc[i*3 + 0], w1 = wc[i*3 + 1], w2 = wc[i*3 + 2];
#pragma unroll
        for (int t = 0; t < 8; t++)
            acc[t] += w0*hs[t][base] + w1*hs[t+1][base] + w2*hs[t+2][base];
    }
#pragma unroll
    for (int t = 0; t < 8; t++)
        y[((long long)(b*TT + tbase + t))*HH + c] = fmaxf(acc[t], 0.f);
}

// ---------------- temporal grouped conv (groups=32, cin/g=4, k=3, pad=1) + relu -----
__global__ void conv_t2_kernel(const float* __restrict__ x, const float* __restrict__ w,
                               const float* __restrict__ bias, float* __restrict__ y)
{
    const int i = blockIdx.x * blockDim.x + threadIdx.x;
    if (i >= BT*W1) return;
    const int c = i & 127;
    const int row = i >> 7;
    const int t = row & (TT-1);
    const int rb = row - t;          // b*T
    const int base = (c >> 2) << 2;
    const float* wp = w + c * 12;    // [4][3]
    float acc = bias[c];
#pragma unroll
    for (int d = 0; d < 3; d++) {
        const int ts = t + d - 1;
        if (ts >= 0 && ts < TT) {
            const float* xr = x + ((long long)(rb + ts))*W1 + base;
#pragma unroll
            for (int ii = 0; ii < 4; ii++)
                acc += wp[ii*3 + d] * xr[ii];
        }
    }
    y[i] = fmaxf(acc, 0.f);
}

// ---------------- row squared-norms ----------------
__global__ void rownorm_kernel(const float* __restrict__ h, float* __restrict__ xx)
{
    const int warp = (blockIdx.x * blockDim.x + threadIdx.x) >> 5;
    const int lane = threadIdx.x & 31;
    if (warp >= BT) return;
    const float* r = h + (long long)warp * HH;
    float s = 0.f;
#pragma unroll
    for (int c = lane; c < HH; c += 32) { float v = r[c]; s += v*v; }
#pragma unroll
    for (int off = 16; off; off >>= 1) s += __shfl_xor_sync(0xffffffffu, s, off);
    if (lane == 0) xx[warp] = s;
}

// ---------------- top-3 of dist over s, stable jax tie-break -----------------
__device__ __forceinline__ void top3_insert(float v, int i, float tv[3], int ti[3])
{
    if (v > tv[0] || (v == tv[0] && i < ti[0])) {
        tv[2]=tv[1]; ti[2]=ti[1]; tv[1]=tv[0]; ti[1]=ti[0]; tv[0]=v; ti[0]=i;
    } else if (v > tv[1] || (v == tv[1] && i < ti[1])) {
        tv[2]=tv[1]; ti[2]=ti[1]; tv[1]=v; ti[1]=i;
    } else if (v > tv[2] || (v == tv[2] && i < ti[2])) {
        tv[2]=v; ti[2]=i;
    }
}

__global__ void top3_kernel(const float* __restrict__ inner, const float* __restrict__ xx,
                            int* __restrict__ idx)
{
    const int warp = (blockIdx.x * blockDim.x + threadIdx.x) >> 5;
    const int lane = threadIdx.x & 31;
    if (warp >= BT) return;
    const int b = warp >> 10;
    const int t = warp & (TT-1);
    const float* row = inner + ((long long)b*TT + t)*TT;
    const float* xb = xx + b*TT;
    const float xt = xb[t];
    float tv[3] = {-FLT_MAX, -FLT_MAX, -FLT_MAX};
    int   ti[3] = {INT_MAX, INT_MAX, INT_MAX};
    for (int s = lane; s < TT; s += 32)
        top3_insert(2.f*row[s] - xt - xb[s], s, tv, ti);
#pragma unroll
    for (int off = 16; off; off >>= 1) {
        float ov[3]; int oi[3];
#pragma unroll
        for (int j = 0; j < 3; j++) {
            ov[j] = __shfl_xor_sync(0xffffffffu, tv[j], off);
            oi[j] = __shfl_xor_sync(0xffffffffu, ti[j], off);
        }
#pragma unroll
        for (int j = 0; j < 3; j++) top3_insert(ov[j], oi[j], tv, ti);
    }
    if (lane == 0) {
        idx[warp*3 + 0] = ti[0];
        idx[warp*3 + 1] = ti[1];
        idx[warp*3 + 2] = ti[2];
    }
}

// ---------------- gather graph feature f = [neighbor, center] ----------------
__global__ void gather_kernel(const float* __restrict__ h, const int* __restrict__ idx,
                              float* __restrict__ f)
{
    const int r = blockIdx.x;          // 0..BTK-1
    const int tid = threadIdx.x;       // 128 threads -> 128 float4 = 512 floats
    const int bt = r / 3;
    const int b = bt >> 10;
    const int j = idx[r];
    const float4* hn = (const float4*)(h + ((long long)(b*TT + j))*HH);
    const float4* hc = (const float4*)(h + (long long)bt*HH);
    float4* fr = (float4*)(f + (long long)r * (2*HH));
    fr[tid] = (tid < 64) ? hn[tid] : hc[tid - 64];
}

// ---------------- semantic grouped 1x1 (groups=32, 4->4) + relu -------------
__global__ void s2_kernel(const float* __restrict__ x, const float* __restrict__ w,
                          const float* __restrict__ bias, float* __restrict__ y)
{
    const int i = blockIdx.x * blockDim.x + threadIdx.x;
    if (i >= BTK*W1) return;
    const int c = i & 127;
    const int r = i >> 7;
    const int base = (c >> 2) << 2;
    const float* xr = x + (long long)r*W1 + base;
    const float* wp = w + c*4;
    float acc = bias[c] + wp[0]*xr[0] + wp[1]*xr[1] + wp[2]*xr[2] + wp[3]*xr[3];
    y[i] = fmaxf(acc, 0.f);
}

// ---------------- fuse: relu(temporal + identity + max_k semantic) ----------
__global__ void fuse_kernel(const float* __restrict__ t3, const float* __restrict__ hin,
                            const float* __restrict__ s3, float* __restrict__ out)
{
    const int i = blockIdx.x * blockDim.x + threadIdx.x;
    if (i >= BT*HH) return;
    const int r = i >> 8;
    const int c = i & 255;
    const float* sr = s3 + ((long long)r*3)*HH + c;
    float m = fmaxf(fmaxf(sr[0], sr[HH]), sr[2*HH]);
    out[i] = fmaxf(t3[i] + hin[i] + m, 0.f);
}

// ---------------- host orchestration ----------------
static inline void gemm(const float* A, const float* W, const float* bias, float* C,
                        int M, int N, int Kd, bool relu, bool has_bias,
                        int batches = 1, long long sA = 0, long long sB = 0, long long sC = 0)
{
    dim3 grid((N + 127) / 128, M / 128, batches);
    if (has_bias) {
        if (relu) sgemm_nt_kernel<true,  true ><<<grid, 256>>>(A, W, bias, C, M, N, Kd, sA, sB, sC);
        else      sgemm_nt_kernel<false, true ><<<grid, 256>>>(A, W, bias, C, M, N, Kd, sA, sB, sC);
    } else {
        if (relu) sgemm_nt_kernel<true,  false><<<grid, 256>>>(A, W, bias, C, M, N, Kd, sA, sB, sC);
        else      sgemm_nt_kernel<false, false><<<grid, 256>>>(A, W, bias, C, M, N, Kd, sA, sB, sC);
    }
}

extern "C" void kernel_launch(void* const* d_in, const int* in_sizes, int n_in,
                              void* d_out, int out_size)
{
    const float* x       = (const float*)d_in[0];
    const float* fc_in_w = (const float*)d_in[1];
    const float* fc_in_b = (const float*)d_in[2];
    const float* conv_w  = (const float*)d_in[3];
    const float* conv_b  = (const float*)d_in[4];
    const float* t1_w    = (const float*)d_in[5];
    const float* t1_b    = (const float*)d_in[6];
    const float* t2_w    = (const float*)d_in[7];
    const float* t2_b    = (const float*)d_in[8];
    const float* t3_w    = (const float*)d_in[9];
    const float* t3_b    = (const float*)d_in[10];
    const float* s1_w    = (const float*)d_in[11];
    const float* s1_b    = (const float*)d_in[12];
    const float* s2_w    = (const float*)d_in[13];
    const float* s2_b    = (const float*)d_in[14];
    const float* s3_w    = (const float*)d_in[15];
    const float* s3_b    = (const float*)d_in[16];
    const float* fc_w    = (const float*)d_in[17];
    const float* fc_b    = (const float*)d_in[18];
    float* out = (float*)d_out;

    float *hA, *hB, *t1, *t2, *t3, *xx, *inner, *f, *s1, *s2, *s3;
    int *idx;
    cudaGetSymbolAddress((void**)&hA, g_hA);
    cudaGetSymbolAddress((void**)&hB, g_hB);
    cudaGetSymbolAddress((void**)&t1, g_t1);
    cudaGetSymbolAddress((void**)&t2, g_t2);
    cudaGetSymbolAddress((void**)&t3, g_t3);
    cudaGetSymbolAddress((void**)&xx, g_xx);
    cudaGetSymbolAddress((void**)&inner, g_inner);
    cudaGetSymbolAddress((void**)&f, g_f);
    cudaGetSymbolAddress((void**)&s1, g_s1);
    cudaGetSymbolAddress((void**)&s2, g_s2);
    cudaGetSymbolAddress((void**)&s3, g_s3);
    cudaGetSymbolAddress((void**)&idx, g_idx);

    // fc_in + relu: [BT,768] @ [256,768]^T -> hB
    gemm(x, fc_in_w, fc_in_b, hB, BT, HH, FEAT, true, true);
    // backbone grouped conv + relu: hB -> hA
    conv_backbone_kernel<<<BB * (TT/8), 256>>>(hB, conv_w, conv_b, hA);

    for (int l = 0; l < LL; l++) {
        const float* cur = (l == 0) ? hA : hB;
        float*       nxt = (l == 0) ? hB : hA;

        // ---- kNN graph ----
        rownorm_kernel<<<BT/8, 256>>>(cur, xx);
        // batched inner = H_b @ H_b^T  (16 x [1024,1024,256])
        gemm(cur, cur, nullptr, inner, TT, TT, HH, false, false,
             BB, (long long)TT*HH, (long long)TT*HH, (long long)TT*TT);
        top3_kernel<<<BT/8, 256>>>(inner, xx, idx);

        // ---- temporal branch ----
        gemm(cur, t1_w + l*W1*HH, t1_b + l*W1, t1, BT, W1, HH, true, true);
        conv_t2_kernel<<<(BT*W1 + 255)/256, 256>>>(t1, t2_w + l*W1*4*3, t2_b + l*W1, t2);
        gemm(t2, t3_w + l*HH*W1, t3_b + l*HH, t3, BT, HH, W1, false, true);

        // ---- semantic branch ----
        gather_kernel<<<BTK, 128>>>(cur, idx, f);
        gemm(f,  s1_w + l*W1*2*HH, s1_b + l*W1, s1, BTK, W1, 2*HH, true, true);
        s2_kernel<<<(BTK*W1 + 255)/256, 256>>>(s1, s2_w + l*W1*4, s2_b + l*W1, s2);
        gemm(s2, s3_w + l*HH*W1, s3_b + l*HH, s3, BTK, HH, W1, false, true);

        // ---- fuse ----
        fuse_kernel<<<(BT*HH + 255)/256, 256>>>(t3, cur, s3, nxt);
    }

    // final fc: [BT,256] @ [50,256]^T -> out
    gemm(hA, fc_w, fc_b, out, BT, CC, HH, false, true);
}

// round 3
// speedup vs baseline: 1.8215x; 1.8215x over previous
#include <cuda_runtime.h>
#include <cfloat>
#include <climits>
#include <cstdint>

// ---------------- problem constants ----------------
#define BB   16
#define TT   1024
#define FEAT 768
#define HH   256
#define CC   50
#define LL   2
#define W1   128
#define GG   32
#define KK   3
#define BT   (BB*TT)        // 16384
#define BTK  (BT*KK)        // 49152

// ---------------- scratch (device globals; no allocs allowed) ----------------
__device__ float g_hA[BT*HH];
__device__ float g_hB[BT*HH];
__device__ float g_t1[BT*W1];
__device__ float g_t2[BT*W1];
__device__ float g_t3[BT*HH];
__device__ float g_xx[BT];
__device__ int   g_idx[BT*KK];
__device__ float g_inner[BB*TT*TT];   // 64 MB
__device__ float g_f[BTK*2*HH];       // 96 MB
__device__ float g_s1[BTK*W1];
__device__ float g_s2[BTK*W1];
__device__ float g_s3[BTK*HH];

// ---------------- tf32 helpers ----------------
__device__ __forceinline__ float f2tf32(float f) {
    uint32_t r;
    asm("cvt.rna.tf32.f32 %0, %1;" : "=r"(r) : "f"(f));
    return __uint_as_float(r);
}

__device__ __forceinline__ void mma_tf32(float* c, const float* a, const float* b) {
    asm volatile(
        "mma.sync.aligned.m16n8k8.row.col.f32.tf32.tf32.f32 "
        "{%0,%1,%2,%3}, {%4,%5,%6,%7}, {%8,%9}, {%0,%1,%2,%3};"
        : "+f"(c[0]), "+f"(c[1]), "+f"(c[2]), "+f"(c[3])
        : "r"(__float_as_uint(a[0])), "r"(__float_as_uint(a[1])),
          "r"(__float_as_uint(a[2])), "r"(__float_as_uint(a[3])),
          "r"(__float_as_uint(b[0])), "r"(__float_as_uint(b[1])));
}

// ---------------- tf32 mma.sync GEMM: C = act(A[M,K] @ W[N,K]^T + bias) -----
// CTA tile 128x128, K-chunk 32, 8 warps (2x4), warp tile 64x32.
// Smem layouts: As[m][kpad=36], Bs[n][kpad=36] per stage; double buffered.
// Requires M % 128 == 0, K % 32 == 0. N arbitrary (guarded).
#define KC     32
#define KPAD   36
#define ATILE  (128*KPAD)           // floats per stage per operand
#define SMEMF  (4*ATILE)            // 2 stages x (A,B) = 18432 floats = 72 KB

template<bool RELU, bool HAS_BIAS>
__global__ void __launch_bounds__(256)
mma_gemm_kernel(const float* __restrict__ A, const float* __restrict__ Bw,
                const float* __restrict__ bias, float* __restrict__ C,
                int M, int N, int Kd,
                long long strideA, long long strideB, long long strideC)
{
    extern __shared__ float sm[];
    const int tid  = threadIdx.x;
    const int wid  = tid >> 5;
    const int lane = tid & 31;
    const int gr   = lane >> 2;      // groupID 0..7
    const int tig  = lane & 3;       // thread-in-group 0..3
    const int warp_m = wid & 1;      // 0..1 (M direction, 64 each)
    const int warp_n = wid >> 1;     // 0..3 (N direction, 32 each)

    const int m0 = blockIdx.y * 128;
    const int n0 = blockIdx.x * 128;
    const int batch = blockIdx.z;
    A  += (long long)batch * strideA;
    Bw += (long long)batch * strideB;
    C  += (long long)batch * strideC;

    // loader indices: 1024 float4 per operand chunk, 4 per thread
    const int lrow = tid >> 3;                 // base row step 32
    const int lcol = (tid & 7) * 4;            // k column

    float acc[4][4][4];
#pragma unroll
    for (int i = 0; i < 4; i++)
#pragma unroll
        for (int j = 0; j < 4; j++)
#pragma unroll
            for (int q = 0; q < 4; q++) acc[i][j][q] = 0.f;

    const int nch = Kd / KC;

    float4 va[4], vb[4];
    // ---- prologue: load chunk 0 ----
#pragma unroll
    for (int it = 0; it < 4; it++) {
        const int row = lrow + it * 32;
        va[it] = *(const float4*)(A + (long long)(m0 + row) * Kd + lcol);
        vb[it] = (n0 + row < N)
               ? *(const float4*)(Bw + (long long)(n0 + row) * Kd + lcol)
               : make_float4(0.f, 0.f, 0.f, 0.f);
    }
    {
        float* As = sm;
        float* Bs = sm + ATILE;
#pragma unroll
        for (int it = 0; it < 4; it++) {
            const int row = lrow + it * 32;
            float* pa = As + row * KPAD + lcol;
            pa[0] = f2tf32(va[it].x); pa[1] = f2tf32(va[it].y);
            pa[2] = f2tf32(va[it].z); pa[3] = f2tf32(va[it].w);
            float* pb = Bs + row * KPAD + lcol;
            pb[0] = f2tf32(vb[it].x); pb[1] = f2tf32(vb[it].y);
            pb[2] = f2tf32(vb[it].z); pb[3] = f2tf32(vb[it].w);
        }
    }
    __syncthreads();

    for (int i = 0; i < nch; i++) {
        const int s = i & 1;
        const bool more = (i + 1 < nch);
        if (more) {
            const int kt = (i + 1) * KC;
#pragma unroll
            for (int it = 0; it < 4; it++) {
                const int row = lrow + it * 32;
                va[it] = *(const float4*)(A + (long long)(m0 + row) * Kd + kt + lcol);
                vb[it] = (n0 + row < N)
                       ? *(const float4*)(Bw + (long long)(n0 + row) * Kd + kt + lcol)
                       : make_float4(0.f, 0.f, 0.f, 0.f);
            }
        }

        const float* As = sm + s * 2 * ATILE;
        const float* Bs = As + ATILE;
#pragma unroll
        for (int kk = 0; kk < 4; kk++) {
            const int kb = kk * 8;
            float af[4][4];
#pragma unroll
            for (int mf = 0; mf < 4; mf++) {
                const float* p = As + (warp_m * 64 + mf * 16 + gr) * KPAD + kb + tig;
                af[mf][0] = p[0];
                af[mf][1] = p[8 * KPAD];
                af[mf][2] = p[4];
                af[mf][3] = p[8 * KPAD + 4];
            }
            float bf[4][2];
#pragma unroll
            for (int nf = 0; nf < 4; nf++) {
                const float* p = Bs + (warp_n * 32 + nf * 8 + gr) * KPAD + kb + tig;
                bf[nf][0] = p[0];
                bf[nf][1] = p[4];
            }
#pragma unroll
            for (int mf = 0; mf < 4; mf++)
#pragma unroll
                for (int nf = 0; nf < 4; nf++)
                    mma_tf32(acc[mf][nf], af[mf], bf[nf]);
        }

        if (more) {
            float* Aw = sm + (s ^ 1) * 2 * ATILE;
            float* Bw2 = Aw + ATILE;
#pragma unroll
            for (int it = 0; it < 4; it++) {
                const int row = lrow + it * 32;
                float* pa = Aw + row * KPAD + lcol;
                pa[0] = f2tf32(va[it].x); pa[1] = f2tf32(va[it].y);
                pa[2] = f2tf32(va[it].z); pa[3] = f2tf32(va[it].w);
                float* pb = Bw2 + row * KPAD + lcol;
                pb[0] = f2tf32(vb[it].x); pb[1] = f2tf32(vb[it].y);
                pb[2] = f2tf32(vb[it].z); pb[3] = f2tf32(vb[it].w);
            }
            __syncthreads();
        }
    }

    // ---- epilogue: direct register stores ----
#pragma unroll
    for (int mf = 0; mf < 4; mf++) {
        const int m = m0 + warp_m * 64 + mf * 16 + gr;
#pragma unroll
        for (int nf = 0; nf < 4; nf++) {
            const int n = n0 + warp_n * 32 + nf * 8 + tig * 2;
            float b0 = 0.f, b1 = 0.f;
            if (HAS_BIAS) {
                if (n     < N) b0 = bias[n];
                if (n + 1 < N) b1 = bias[n + 1];
            }
            float v0 = acc[mf][nf][0] + b0;
            float v1 = acc[mf][nf][1] + b1;
            float v2 = acc[mf][nf][2] + b0;
            float v3 = acc[mf][nf][3] + b1;
            if (RELU) {
                v0 = fmaxf(v0, 0.f); v1 = fmaxf(v1, 0.f);
                v2 = fmaxf(v2, 0.f); v3 = fmaxf(v3, 0.f);
            }
            float* r0 = C + (long long)m * N;
            float* r1 = C + (long long)(m + 8) * N;
            if (n + 1 < N) {
                *(float2*)(r0 + n) = make_float2(v0, v1);
                *(float2*)(r1 + n) = make_float2(v2, v3);
            } else if (n < N) {
                r0[n] = v0;
                r1[n] = v2;
            }
        }
    }
}

// ---------------- backbone grouped conv1d (groups=4, cin/g=64, k=3, pad=1) + relu ----
__global__ void __launch_bounds__(256)
conv_backbone_kernel(const float* __restrict__ x, const float* __restrict__ w,
                     const float* __restrict__ bias, float* __restrict__ y)
{
    const int b = blockIdx.x >> 7;
    const int tbase = (blockIdx.x & 127) << 3;
    __shared__ float hs[10][HH];
    const int tid = threadIdx.x;
#pragma unroll
    for (int r = 0; r < 10; r++) {
        const int t = tbase - 1 + r;
        hs[r][tid] = (t >= 0 && t < TT) ? x[((long long)(b*TT + t))*HH + tid] : 0.f;
    }
    __syncthreads();
    const int c = tid;
    const int g = c >> 6;
    const float* wc = w + c * 192;
    float acc[8];
    const float bb = bias[c];
#pragma unroll
    for (int t = 0; t < 8; t++) acc[t] = bb;
    for (int i = 0; i < 64; i++) {
        const int base = g*64 + i;
        const float w0 = wc[i*3 + 0], w1 = wc[i*3 + 1], w2 = wc[i*3 + 2];
#pragma unroll
        for (int t = 0; t < 8; t++)
            acc[t] += w0*hs[t][base] + w1*hs[t+1][base] + w2*hs[t+2][base];
    }
#pragma unroll
    for (int t = 0; t < 8; t++)
        y[((long long)(b*TT + tbase + t))*HH + c] = fmaxf(acc[t], 0.f);
}

// ---------------- temporal grouped conv (groups=32, cin/g=4, k=3, pad=1) + relu -----
__global__ void conv_t2_kernel(const float* __restrict__ x, const float* __restrict__ w,
                               const float* __restrict__ bias, float* __restrict__ y)
{
    const int i = blockIdx.x * blockDim.x + threadIdx.x;
    if (i >= BT*W1) return;
    const int c = i & 127;
    const int row = i >> 7;
    const int t = row & (TT-1);
    const int rb = row - t;
    const int base = (c >> 2) << 2;
    const float* wp = w + c * 12;
    float acc = bias[c];
#pragma unroll
    for (int d = 0; d < 3; d++) {
        const int ts = t + d - 1;
        if (ts >= 0 && ts < TT) {
            const float* xr = x + ((long long)(rb + ts))*W1 + base;
#pragma unroll
            for (int ii = 0; ii < 4; ii++)
                acc += wp[ii*3 + d] * xr[ii];
        }
    }
    y[i] = fmaxf(acc, 0.f);
}

// ---------------- row squared-norms ----------------
__global__ void rownorm_kernel(const float* __restrict__ h, float* __restrict__ xx)
{
    const int warp = (blockIdx.x * blockDim.x + threadIdx.x) >> 5;
    const int lane = threadIdx.x & 31;
    if (warp >= BT) return;
    const float* r = h + (long long)warp * HH;
    float s = 0.f;
#pragma unroll
    for (int c = lane; c < HH; c += 32) { float v = r[c]; s += v*v; }
#pragma unroll
    for (int off = 16; off; off >>= 1) s += __shfl_xor_sync(0xffffffffu, s, off);
    if (lane == 0) xx[warp] = s;
}

// ---------------- top-3 of dist over s, stable jax tie-break -----------------
__device__ __forceinline__ void top3_insert(float v, int i, float tv[3], int ti[3])
{
    if (v > tv[0] || (v == tv[0] && i < ti[0])) {
        tv[2]=tv[1]; ti[2]=ti[1]; tv[1]=tv[0]; ti[1]=ti[0]; tv[0]=v; ti[0]=i;
    } else if (v > tv[1] || (v == tv[1] && i < ti[1])) {
        tv[2]=tv[1]; ti[2]=ti[1]; tv[1]=v; ti[1]=i;
    } else if (v > tv[2] || (v == tv[2] && i < ti[2])) {
        tv[2]=v; ti[2]=i;
    }
}

__global__ void top3_kernel(const float* __restrict__ inner, const float* __restrict__ xx,
                            int* __restrict__ idx)
{
    const int warp = (blockIdx.x * blockDim.x + threadIdx.x) >> 5;
    const int lane = threadIdx.x & 31;
    if (warp >= BT) return;
    const int b = warp >> 10;
    const int t = warp & (TT-1);
    const float* row = inner + ((long long)b*TT + t)*TT;
    const float* xb = xx + b*TT;
    const float xt = xb[t];
    float tv[3] = {-FLT_MAX, -FLT_MAX, -FLT_MAX};
    int   ti[3] = {INT_MAX, INT_MAX, INT_MAX};
    for (int s = lane; s < TT; s += 32)
        top3_insert(2.f*row[s] - xt - xb[s], s, tv, ti);
#pragma unroll
    for (int off = 16; off; off >>= 1) {
        float ov[3]; int oi[3];
#pragma unroll
        for (int j = 0; j < 3; j++) {
            ov[j] = __shfl_xor_sync(0xffffffffu, tv[j], off);
            oi[j] = __shfl_xor_sync(0xffffffffu, ti[j], off);
        }
#pragma unroll
        for (int j = 0; j < 3; j++) top3_insert(ov[j], oi[j], tv, ti);
    }
    if (lane == 0) {
        idx[warp*3 + 0] = ti[0];
        idx[warp*3 + 1] = ti[1];
        idx[warp*3 + 2] = ti[2];
    }
}

// ---------------- gather graph feature f = [neighbor, center] ----------------
__global__ void gather_kernel(const float* __restrict__ h, const int* __restrict__ idx,
                              float* __restrict__ f)
{
    const int r = blockIdx.x;
    const int tid = threadIdx.x;
    const int bt = r / 3;
    const int b = bt >> 10;
    const int j = idx[r];
    const float4* hn = (const float4*)(h + ((long long)(b*TT + j))*HH);
    const float4* hc = (const float4*)(h + (long long)bt*HH);
    float4* fr = (float4*)(f + (long long)r * (2*HH));
    fr[tid] = (tid < 64) ? hn[tid] : hc[tid - 64];
}

// ---------------- semantic grouped 1x1 (groups=32, 4->4) + relu -------------
__global__ void s2_kernel(const float* __restrict__ x, const float* __restrict__ w,
                          const float* __restrict__ bias, float* __restrict__ y)
{
    const int i = blockIdx.x * blockDim.x + threadIdx.x;
    if (i >= BTK*W1) return;
    const int c = i & 127;
    const int r = i >> 7;
    const int base = (c >> 2) << 2;
    const float* xr = x + (long long)r*W1 + base;
    const float* wp = w + c*4;
    float acc = bias[c] + wp[0]*xr[0] + wp[1]*xr[1] + wp[2]*xr[2] + wp[3]*xr[3];
    y[i] = fmaxf(acc, 0.f);
}

// ---------------- fuse: relu(temporal + identity + max_k semantic) ----------
__global__ void fuse_kernel(const float* __restrict__ t3, const float* __restrict__ hin,
                            const float* __restrict__ s3, float* __restrict__ out)
{
    const int i = blockIdx.x * blockDim.x + threadIdx.x;
    if (i >= BT*HH) return;
    const int r = i >> 8;
    const int c = i & 255;
    const float* sr = s3 + ((long long)r*3)*HH + c;
    float m = fmaxf(fmaxf(sr[0], sr[HH]), sr[2*HH]);
    out[i] = fmaxf(t3[i] + hin[i] + m, 0.f);
}

// ---------------- host orchestration ----------------
#define SMEM_BYTES (SMEMF * 4)

static inline void gemm(const float* A, const float* W, const float* bias, float* C,
                        int M, int N, int Kd, bool relu, bool has_bias,
                        int batches = 1, long long sA = 0, long long sB = 0, long long sC = 0)
{
    dim3 grid((N + 127) / 128, M / 128, batches);
    if (has_bias) {
        if (relu) {
            cudaFuncSetAttribute(mma_gemm_kernel<true, true>,
                                 cudaFuncAttributeMaxDynamicSharedMemorySize, SMEM_BYTES);
            mma_gemm_kernel<true, true><<<grid, 256, SMEM_BYTES>>>(A, W, bias, C, M, N, Kd, sA, sB, sC);
        } else {
            cudaFuncSetAttribute(mma_gemm_kernel<false, true>,
                                 cudaFuncAttributeMaxDynamicSharedMemorySize, SMEM_BYTES);
            mma_gemm_kernel<false, true><<<grid, 256, SMEM_BYTES>>>(A, W, bias, C, M, N, Kd, sA, sB, sC);
        }
    } else {
        cudaFuncSetAttribute(mma_gemm_kernel<false, false>,
                             cudaFuncAttributeMaxDynamicSharedMemorySize, SMEM_BYTES);
        mma_gemm_kernel<false, false><<<grid, 256, SMEM_BYTES>>>(A, W, bias, C, M, N, Kd, sA, sB, sC);
    }
}

extern "C" void kernel_launch(void* const* d_in, const int* in_sizes, int n_in,
                              void* d_out, int out_size)
{
    const float* x       = (const float*)d_in[0];
    const float* fc_in_w = (const float*)d_in[1];
    const float* fc_in_b = (const float*)d_in[2];
    const float* conv_w  = (const float*)d_in[3];
    const float* conv_b  = (const float*)d_in[4];
    const float* t1_w    = (const float*)d_in[5];
    const float* t1_b    = (const float*)d_in[6];
    const float* t2_w    = (const float*)d_in[7];
    const float* t2_b    = (const float*)d_in[8];
    const float* t3_w    = (const float*)d_in[9];
    const float* t3_b    = (const float*)d_in[10];
    const float* s1_w    = (const float*)d_in[11];
    const float* s1_b    = (const float*)d_in[12];
    const float* s2_w    = (const float*)d_in[13];
    const float* s2_b    = (const float*)d_in[14];
    const float* s3_w    = (const float*)d_in[15];
    const float* s3_b    = (const float*)d_in[16];
    const float* fc_w    = (const float*)d_in[17];
    const float* fc_b    = (const float*)d_in[18];
    float* out = (float*)d_out;

    float *hA, *hB, *t1, *t2, *t3, *xx, *inner, *f, *s1, *s2, *s3;
    int *idx;
    cudaGetSymbolAddress((void**)&hA, g_hA);
    cudaGetSymbolAddress((void**)&hB, g_hB);
    cudaGetSymbolAddress((void**)&t1, g_t1);
    cudaGetSymbolAddress((void**)&t2, g_t2);
    cudaGetSymbolAddress((void**)&t3, g_t3);
    cudaGetSymbolAddress((void**)&xx, g_xx);
    cudaGetSymbolAddress((void**)&inner, g_inner);
    cudaGetSymbolAddress((void**)&f, g_f);
    cudaGetSymbolAddress((void**)&s1, g_s1);
    cudaGetSymbolAddress((void**)&s2, g_s2);
    cudaGetSymbolAddress((void**)&s3, g_s3);
    cudaGetSymbolAddress((void**)&idx, g_idx);

    // fc_in + relu: [BT,768] @ [256,768]^T -> hB
    gemm(x, fc_in_w, fc_in_b, hB, BT, HH, FEAT, true, true);
    // backbone grouped conv + relu: hB -> hA
    conv_backbone_kernel<<<BB * (TT/8), 256>>>(hB, conv_w, conv_b, hA);

    for (int l = 0; l < LL; l++) {
        const float* cur = (l == 0) ? hA : hB;
        float*       nxt = (l == 0) ? hB : hA;

        // ---- kNN graph ----
        rownorm_kernel<<<BT/8, 256>>>(cur, xx);
        gemm(cur, cur, nullptr, inner, TT, TT, HH, false, false,
             BB, (long long)TT*HH, (long long)TT*HH, (long long)TT*TT);
        top3_kernel<<<BT/8, 256>>>(inner, xx, idx);

        // ---- temporal branch ----
        gemm(cur, t1_w + l*W1*HH, t1_b + l*W1, t1, BT, W1, HH, true, true);
        conv_t2_kernel<<<(BT*W1 + 255)/256, 256>>>(t1, t2_w + l*W1*4*3, t2_b + l*W1, t2);
        gemm(t2, t3_w + l*HH*W1, t3_b + l*HH, t3, BT, HH, W1, false, true);

        // ---- semantic branch ----
        gather_kernel<<<BTK, 128>>>(cur, idx, f);
        gemm(f,  s1_w + l*W1*2*HH, s1_b + l*W1, s1, BTK, W1, 2*HH, true, true);
        s2_kernel<<<(BTK*W1 + 255)/256, 256>>>(s1, s2_w + l*W1*4, s2_b + l*W1, s2);
        gemm(s2, s3_w + l*HH*W1, s3_b + l*HH, s3, BTK, HH, W1, false, true);

        // ---- fuse ----
        fuse_kernel<<<(BT*HH + 255)/256, 256>>>(t3, cur, s3, nxt);
    }

    // final fc: [BT,256] @ [50,256]^T -> out
    gemm(hA, fc_w, fc_b, out, BT, CC, HH, false, true);
}

// round 4
// speedup vs baseline: 1.9923x; 1.0938x over previous
#include <cuda_runtime.h>
#include <cfloat>
#include <climits>
#include <cstdint>

// ---------------- problem constants ----------------
#define BB   16
#define TT   1024
#define FEAT 768
#define HH   256
#define CC   50
#define LL   2
#define W1   128
#define GG   32
#define KK   3
#define BT   (BB*TT)        // 16384
#define BTK  (BT*KK)        // 49152

// ---------------- scratch (device globals; no allocs allowed) ----------------
__device__ float g_hA[BT*HH];
__device__ float g_hB[BT*HH];
__device__ float g_t1[BT*W1];
__device__ float g_t2[BT*W1];
__device__ float g_t3[BT*HH];
__device__ float g_xx[BT];
__device__ int   g_idx[BT*KK];
__device__ float g_pv[BT*24];         // per-tile top3 partial values
__device__ int   g_pi[BT*24];         // per-tile top3 partial indices
__device__ float g_u[BT*W1];          // h @ Wn^T
__device__ float g_v[BT*W1];          // h @ Wc^T + b
__device__ float g_s1[BTK*W1];
__device__ float g_s2[BTK*W1];
__device__ float g_s3[BTK*HH];

// ---------------- tf32 helpers ----------------
__device__ __forceinline__ float f2tf32(float f) {
    uint32_t r;
    asm("cvt.rna.tf32.f32 %0, %1;" : "=r"(r) : "f"(f));
    return __uint_as_float(r);
}

__device__ __forceinline__ void mma_tf32(float* c, const float* a, const float* b) {
    asm volatile(
        "mma.sync.aligned.m16n8k8.row.col.f32.tf32.tf32.f32 "
        "{%0,%1,%2,%3}, {%4,%5,%6,%7}, {%8,%9}, {%0,%1,%2,%3};"
        : "+f"(c[0]), "+f"(c[1]), "+f"(c[2]), "+f"(c[3])
        : "r"(__float_as_uint(a[0])), "r"(__float_as_uint(a[1])),
          "r"(__float_as_uint(a[2])), "r"(__float_as_uint(a[3])),
          "r"(__float_as_uint(b[0])), "r"(__float_as_uint(b[1])));
}

// ---------------- top3 with stable jax tie-break ----------------
__device__ __forceinline__ void top3_insert(float v, int i, float tv[3], int ti[3])
{
    if (v > tv[0] || (v == tv[0] && i < ti[0])) {
        tv[2]=tv[1]; ti[2]=ti[1]; tv[1]=tv[0]; ti[1]=ti[0]; tv[0]=v; ti[0]=i;
    } else if (v > tv[1] || (v == tv[1] && i < ti[1])) {
        tv[2]=tv[1]; ti[2]=ti[1]; tv[1]=v; ti[1]=i;
    } else if (v > tv[2] || (v == tv[2] && i < ti[2])) {
        tv[2]=v; ti[2]=i;
    }
}

__device__ __forceinline__ void top3_quad_merge(float tv[3], int ti[3])
{
#pragma unroll
    for (int off = 1; off <= 2; off <<= 1) {
        float ov[3]; int oi[3];
#pragma unroll
        for (int j = 0; j < 3; j++) {
            ov[j] = __shfl_xor_sync(0xffffffffu, tv[j], off);
            oi[j] = __shfl_xor_sync(0xffffffffu, ti[j], off);
        }
#pragma unroll
        for (int j = 0; j < 3; j++) top3_insert(ov[j], oi[j], tv, ti);
    }
}

// ---------------- tf32 mma.sync GEMM: C = act(A[M,K] @ W[N,K]^T + bias) -----
// CTA tile 128x128, K-chunk 32, 8 warps (2x4), warp tile 64x32, double buffered.
// Requires M % 128 == 0, K % 32 == 0. N arbitrary (guarded). B row stride = ldB.
#define KC     32
#define KPAD   36
#define ATILE  (128*KPAD)
#define SMEMF  (4*ATILE)
#define SMEM_BYTES (SMEMF * 4)

template<bool RELU, bool HAS_BIAS>
__global__ void __launch_bounds__(256)
mma_gemm_kernel(const float* __restrict__ A, const float* __restrict__ Bw,
                const float* __restrict__ bias, float* __restrict__ C,
                int M, int N, int Kd, int ldB,
                long long strideA, long long strideB, long long strideC)
{
    extern __shared__ float sm[];
    const int tid  = threadIdx.x;
    const int wid  = tid >> 5;
    const int lane = tid & 31;
    const int gr   = lane >> 2;
    const int tig  = lane & 3;
    const int warp_m = wid & 1;
    const int warp_n = wid >> 1;

    const int m0 = blockIdx.y * 128;
    const int n0 = blockIdx.x * 128;
    const int batch = blockIdx.z;
    A  += (long long)batch * strideA;
    Bw += (long long)batch * strideB;
    C  += (long long)batch * strideC;

    const int lrow = tid >> 3;
    const int lcol = (tid & 7) * 4;

    float acc[4][4][4];
#pragma unroll
    for (int i = 0; i < 4; i++)
#pragma unroll
        for (int j = 0; j < 4; j++)
#pragma unroll
            for (int q = 0; q < 4; q++) acc[i][j][q] = 0.f;

    const int nch = Kd / KC;

    float4 va[4], vb[4];
#pragma unroll
    for (int it = 0; it < 4; it++) {
        const int row = lrow + it * 32;
        va[it] = *(const float4*)(A + (long long)(m0 + row) * Kd + lcol);
        vb[it] = (n0 + row < N)
               ? *(const float4*)(Bw + (long long)(n0 + row) * ldB + lcol)
               : make_float4(0.f, 0.f, 0.f, 0.f);
    }
    {
        float* As = sm;
        float* Bs = sm + ATILE;
#pragma unroll
        for (int it = 0; it < 4; it++) {
            const int row = lrow + it * 32;
            float* pa = As + row * KPAD + lcol;
            pa[0] = f2tf32(va[it].x); pa[1] = f2tf32(va[it].y);
            pa[2] = f2tf32(va[it].z); pa[3] = f2tf32(va[it].w);
            float* pb = Bs + row * KPAD + lcol;
            pb[0] = f2tf32(vb[it].x); pb[1] = f2tf32(vb[it].y);
            pb[2] = f2tf32(vb[it].z); pb[3] = f2tf32(vb[it].w);
        }
    }
    __syncthreads();

    for (int i = 0; i < nch; i++) {
        const int s = i & 1;
        const bool more = (i + 1 < nch);
        if (more) {
            const int kt = (i + 1) * KC;
#pragma unroll
            for (int it = 0; it < 4; it++) {
                const int row = lrow + it * 32;
                va[it] = *(const float4*)(A + (long long)(m0 + row) * Kd + kt + lcol);
                vb[it] = (n0 + row < N)
                       ? *(const float4*)(Bw + (long long)(n0 + row) * ldB + kt + lcol)
                       : make_float4(0.f, 0.f, 0.f, 0.f);
            }
        }

        const float* As = sm + s * 2 * ATILE;
        const float* Bs = As + ATILE;
#pragma unroll
        for (int kk = 0; kk < 4; kk++) {
            const int kb = kk * 8;
            float af[4][4];
#pragma unroll
            for (int mf = 0; mf < 4; mf++) {
                const float* p = As + (warp_m * 64 + mf * 16 + gr) * KPAD + kb + tig;
                af[mf][0] = p[0];
                af[mf][1] = p[8 * KPAD];
                af[mf][2] = p[4];
                af[mf][3] = p[8 * KPAD + 4];
            }
            float bf[4][2];
#pragma unroll
            for (int nf = 0; nf < 4; nf++) {
                const float* p = Bs + (warp_n * 32 + nf * 8 + gr) * KPAD + kb + tig;
                bf[nf][0] = p[0];
                bf[nf][1] = p[4];
            }
#pragma unroll
            for (int mf = 0; mf < 4; mf++)
#pragma unroll
                for (int nf = 0; nf < 4; nf++)
                    mma_tf32(acc[mf][nf], af[mf], bf[nf]);
        }

        if (more) {
            float* Aw = sm + (s ^ 1) * 2 * ATILE;
            float* Bw2 = Aw + ATILE;
#pragma unroll
            for (int it = 0; it < 4; it++) {
                const int row = lrow + it * 32;
                float* pa = Aw + row * KPAD + lcol;
                pa[0] = f2tf32(va[it].x); pa[1] = f2tf32(va[it].y);
                pa[2] = f2tf32(va[it].z); pa[3] = f2tf32(va[it].w);
                float* pb = Bw2 + row * KPAD + lcol;
                pb[0] = f2tf32(vb[it].x); pb[1] = f2tf32(vb[it].y);
                pb[2] = f2tf32(vb[it].z); pb[3] = f2tf32(vb[it].w);
            }
            __syncthreads();
        }
    }

#pragma unroll
    for (int mf = 0; mf < 4; mf++) {
        const int m = m0 + warp_m * 64 + mf * 16 + gr;
#pragma unroll
        for (int nf = 0; nf < 4; nf++) {
            const int n = n0 + warp_n * 32 + nf * 8 + tig * 2;
            float b0 = 0.f, b1 = 0.f;
            if (HAS_BIAS) {
                if (n     < N) b0 = bias[n];
                if (n + 1 < N) b1 = bias[n + 1];
            }
            float v0 = acc[mf][nf][0] + b0;
            float v1 = acc[mf][nf][1] + b1;
            float v2 = acc[mf][nf][2] + b0;
            float v3 = acc[mf][nf][3] + b1;
            if (RELU) {
                v0 = fmaxf(v0, 0.f); v1 = fmaxf(v1, 0.f);
                v2 = fmaxf(v2, 0.f); v3 = fmaxf(v3, 0.f);
            }
            float* r0 = C + (long long)m * N;
            float* r1 = C + (long long)(m + 8) * N;
            if (n + 1 < N) {
                *(float2*)(r0 + n) = make_float2(v0, v1);
                *(float2*)(r1 + n) = make_float2(v2, v3);
            } else if (n < N) {
                r0[n] = v0;
                r1[n] = v2;
            }
        }
    }
}

// ---------------- fused inner-product GEMM + per-row partial top3 ----------
// Computes a 128x128 tile of inner = h_b @ h_b^T (tf32), then per-row top3 of
// dist = 2*inner - xx[m] - xx[n] within the tile; writes 3 partials per row
// per column tile to g_pv/g_pi. No inner matrix is materialized.
__global__ void __launch_bounds__(256)
inner_top3_kernel(const float* __restrict__ h, const float* __restrict__ xx,
                  float* __restrict__ pv, int* __restrict__ pi)
{
    extern __shared__ float sm[];
    const int tid  = threadIdx.x;
    const int wid  = tid >> 5;
    const int lane = tid & 31;
    const int gr   = lane >> 2;
    const int tig  = lane & 3;
    const int warp_m = wid & 1;
    const int warp_n = wid >> 1;

    const int m0 = blockIdx.y * 128;
    const int n0 = blockIdx.x * 128;
    const int batch = blockIdx.z;
    const float* A = h + (long long)batch * TT * HH;

    const int lrow = tid >> 3;
    const int lcol = (tid & 7) * 4;

    float acc[4][4][4];
#pragma unroll
    for (int i = 0; i < 4; i++)
#pragma unroll
        for (int j = 0; j < 4; j++)
#pragma unroll
            for (int q = 0; q < 4; q++) acc[i][j][q] = 0.f;

    const int nch = HH / KC;   // 8

    float4 va[4], vb[4];
#pragma unroll
    for (int it = 0; it < 4; it++) {
        const int row = lrow + it * 32;
        va[it] = *(const float4*)(A + (long long)(m0 + row) * HH + lcol);
        vb[it] = *(const float4*)(A + (long long)(n0 + row) * HH + lcol);
    }
    {
        float* As = sm;
        float* Bs = sm + ATILE;
#pragma unroll
        for (int it = 0; it < 4; it++) {
            const int row = lrow + it * 32;
            float* pa = As + row * KPAD + lcol;
            pa[0] = f2tf32(va[it].x); pa[1] = f2tf32(va[it].y);
            pa[2] = f2tf32(va[it].z); pa[3] = f2tf32(va[it].w);
            float* pb = Bs + row * KPAD + lcol;
            pb[0] = f2tf32(vb[it].x); pb[1] = f2tf32(vb[it].y);
            pb[2] = f2tf32(vb[it].z); pb[3] = f2tf32(vb[it].w);
        }
    }
    __syncthreads();

    for (int i = 0; i < nch; i++) {
        const int s = i & 1;
        const bool more = (i + 1 < nch);
        if (more) {
            const int kt = (i + 1) * KC;
#pragma unroll
            for (int it = 0; it < 4; it++) {
                const int row = lrow + it * 32;
                va[it] = *(const float4*)(A + (long long)(m0 + row) * HH + kt + lcol);
                vb[it] = *(const float4*)(A + (long long)(n0 + row) * HH + kt + lcol);
            }
        }

        const float* As = sm + s * 2 * ATILE;
        const float* Bs = As + ATILE;
#pragma unroll
        for (int kk = 0; kk < 4; kk++) {
            const int kb = kk * 8;
            float af[4][4];
#pragma unroll
            for (int mf = 0; mf < 4; mf++) {
                const float* p = As + (warp_m * 64 + mf * 16 + gr) * KPAD + kb + tig;
                af[mf][0] = p[0];
                af[mf][1] = p[8 * KPAD];
                af[mf][2] = p[4];
                af[mf][3] = p[8 * KPAD + 4];
            }
            float bf[4][2];
#pragma unroll
            for (int nf = 0; nf < 4; nf++) {
                const float* p = Bs + (warp_n * 32 + nf * 8 + gr) * KPAD + kb + tig;
                bf[nf][0] = p[0];
                bf[nf][1] = p[4];
            }
#pragma unroll
            for (int mf = 0; mf < 4; mf++)
#pragma unroll
                for (int nf = 0; nf < 4; nf++)
                    mma_tf32(acc[mf][nf], af[mf], bf[nf]);
        }

        if (more) {
            float* Aw = sm + (s ^ 1) * 2 * ATILE;
            float* Bw2 = Aw + ATILE;
#pragma unroll
            for (int it = 0; it < 4; it++) {
                const int row = lrow + it * 32;
                float* pa = Aw + row * KPAD + lcol;
                pa[0] = f2tf32(va[it].x); pa[1] = f2tf32(va[it].y);
                pa[2] = f2tf32(va[it].z); pa[3] = f2tf32(va[it].w);
                float* pb = Bw2 + row * KPAD + lcol;
                pb[0] = f2tf32(vb[it].x); pb[1] = f2tf32(vb[it].y);
                pb[2] = f2tf32(vb[it].z); pb[3] = f2tf32(vb[it].w);
            }
            __syncthreads();
        }
    }

    // ---- epilogue: per-row top3 of dist within this tile ----
    const float* xb = xx + batch * TT;
    __syncthreads();                       // safe to reuse smem
    float* svals = sm;                     // [128][4][3]
    int*   sidx  = (int*)(sm + 1536);      // [128][4][3]

    float xn[8];
#pragma unroll
    for (int nf = 0; nf < 4; nf++) {
        const int n = n0 + warp_n * 32 + nf * 8 + tig * 2;
        xn[nf * 2]     = xb[n];
        xn[nf * 2 + 1] = xb[n + 1];
    }

#pragma unroll
    for (int mf = 0; mf < 4; mf++) {
        const int r0 = warp_m * 64 + mf * 16 + gr;
        const float xv0 = xb[m0 + r0];
        const float xv1 = xb[m0 + r0 + 8];
        float tv0[3] = {-FLT_MAX, -FLT_MAX, -FLT_MAX};
        float tv1[3] = {-FLT_MAX, -FLT_MAX, -FLT_MAX};
        int ti0[3] = {INT_MAX, INT_MAX, INT_MAX};
        int ti1[3] = {INT_MAX, INT_MAX, INT_MAX};
#pragma unroll
        for (int nf = 0; nf < 4; nf++) {
            const int n = n0 + warp_n * 32 + nf * 8 + tig * 2;
            top3_insert(2.f * acc[mf][nf][0] - xv0 - xn[nf*2],   n,     tv0, ti0);
            top3_insert(2.f * acc[mf][nf][1] - xv0 - xn[nf*2+1], n + 1, tv0, ti0);
            top3_insert(2.f * acc[mf][nf][2] - xv1 - xn[nf*2],   n,     tv1, ti1);
            top3_insert(2.f * acc[mf][nf][3] - xv1 - xn[nf*2+1], n + 1, tv1, ti1);
        }
        top3_quad_merge(tv0, ti0);
        top3_quad_merge(tv1, ti1);
        if (tig == 0) {
#pragma unroll
            for (int j = 0; j < 3; j++) {
                svals[(r0 * 4 + warp_n) * 3 + j] = tv0[j];
                sidx [(r0 * 4 + warp_n) * 3 + j] = ti0[j];
                svals[((r0 + 8) * 4 + warp_n) * 3 + j] = tv1[j];
                sidx [((r0 + 8) * 4 + warp_n) * 3 + j] = ti1[j];
            }
        }
    }
    __syncthreads();

    if (tid < 128) {
        const int row = tid;
        float tv[3] = {-FLT_MAX, -FLT_MAX, -FLT_MAX};
        int ti[3] = {INT_MAX, INT_MAX, INT_MAX};
#pragma unroll
        for (int w = 0; w < 4; w++)
#pragma unroll
            for (int j = 0; j < 3; j++)
                top3_insert(svals[(row * 4 + w) * 3 + j], sidx[(row * 4 + w) * 3 + j], tv, ti);
        const long long base = (((long long)batch * TT + m0 + row) * 8 + blockIdx.x) * 3;
#pragma unroll
        for (int j = 0; j < 3; j++) { pv[base + j] = tv[j]; pi[base + j] = ti[j]; }
    }
}

// ---------------- final top3 merge over 8 column tiles ----------------
__global__ void top3_final_kernel(const float* __restrict__ pv, const int* __restrict__ pi,
                                  int* __restrict__ idx)
{
    const int bt = blockIdx.x * 256 + threadIdx.x;
    if (bt >= BT) return;
    float tv[3] = {-FLT_MAX, -FLT_MAX, -FLT_MAX};
    int ti[3] = {INT_MAX, INT_MAX, INT_MAX};
    const float* p = pv + (long long)bt * 24;
    const int*   q = pi + (long long)bt * 24;
#pragma unroll
    for (int c = 0; c < 24; c++) top3_insert(p[c], q[c], tv, ti);
    idx[bt*3 + 0] = ti[0];
    idx[bt*3 + 1] = ti[1];
    idx[bt*3 + 2] = ti[2];
}

// ---------------- backbone grouped conv1d (groups=4, cin/g=64, k=3, pad=1) + relu ----
__global__ void __launch_bounds__(256)
conv_backbone_kernel(const float* __restrict__ x, const float* __restrict__ w,
                     const float* __restrict__ bias, float* __restrict__ y)
{
    const int b = blockIdx.x >> 7;
    const int tbase = (blockIdx.x & 127) << 3;
    __shared__ float hs[10][HH];
    const int tid = threadIdx.x;
#pragma unroll
    for (int r = 0; r < 10; r++) {
        const int t = tbase - 1 + r;
        hs[r][tid] = (t >= 0 && t < TT) ? x[((long long)(b*TT + t))*HH + tid] : 0.f;
    }
    __syncthreads();
    const int c = tid;
    const int g = c >> 6;
    const float* wc = w + c * 192;
    float acc[8];
    const float bb = bias[c];
#pragma unroll
    for (int t = 0; t < 8; t++) acc[t] = bb;
    for (int i = 0; i < 64; i++) {
        const int base = g*64 + i;
        const float w0 = wc[i*3 + 0], w1 = wc[i*3 + 1], w2 = wc[i*3 + 2];
#pragma unroll
        for (int t = 0; t < 8; t++)
            acc[t] += w0*hs[t][base] + w1*hs[t+1][base] + w2*hs[t+2][base];
    }
#pragma unroll
    for (int t = 0; t < 8; t++)
        y[((long long)(b*TT + tbase + t))*HH + c] = fmaxf(acc[t], 0.f);
}

// ---------------- temporal grouped conv (groups=32, cin/g=4, k=3, pad=1) + relu -----
__global__ void conv_t2_kernel(const float* __restrict__ x, const float* __restrict__ w,
                               const float* __restrict__ bias, float* __restrict__ y)
{
    const int i = blockIdx.x * blockDim.x + threadIdx.x;
    if (i >= BT*W1) return;
    const int c = i & 127;
    const int row = i >> 7;
    const int t = row & (TT-1);
    const int rb = row - t;
    const int base = (c >> 2) << 2;
    const float* wp = w + c * 12;
    float acc = bias[c];
#pragma unroll
    for (int d = 0; d < 3; d++) {
        const int ts = t + d - 1;
        if (ts >= 0 && ts < TT) {
            const float* xr = x + ((long long)(rb + ts))*W1 + base;
#pragma unroll
            for (int ii = 0; ii < 4; ii++)
                acc += wp[ii*3 + d] * xr[ii];
        }
    }
    y[i] = fmaxf(acc, 0.f);
}

// ---------------- row squared-norms ----------------
__global__ void rownorm_kernel(const float* __restrict__ h, float* __restrict__ xx)
{
    const int warp = (blockIdx.x * blockDim.x + threadIdx.x) >> 5;
    const int lane = threadIdx.x & 31;
    if (warp >= BT) return;
    const float* r = h + (long long)warp * HH;
    float s = 0.f;
#pragma unroll
    for (int c = lane; c < HH; c += 32) { float v = r[c]; s += v*v; }
#pragma unroll
    for (int off = 16; off; off >>= 1) s += __shfl_xor_sync(0xffffffffu, s, off);
    if (lane == 0) xx[warp] = s;
}

// ---------------- s1 = relu(U[neighbor] + V[center])  (bias folded into V) --
__global__ void __launch_bounds__(256)
s1_fuse_kernel(const float* __restrict__ U, const float* __restrict__ V,
               const int* __restrict__ idx, float* __restrict__ s1)
{
    const int tid = threadIdx.x;
    const int r = blockIdx.x * 8 + (tid >> 5);   // row in [0, BTK)
    const int c4 = tid & 31;                     // float4 index within 128 floats
    const int bt = r / 3;
    const int b = bt >> 10;
    const int j = idx[r];
    const float4 u = *(const float4*)(U + ((long long)((b << 10) + j)) * W1 + c4 * 4);
    const float4 v = *(const float4*)(V + (long long)bt * W1 + c4 * 4);
    float4 o;
    o.x = fmaxf(u.x + v.x, 0.f);
    o.y = fmaxf(u.y + v.y, 0.f);
    o.z = fmaxf(u.z + v.z, 0.f);
    o.w = fmaxf(u.w + v.w, 0.f);
    *(float4*)(s1 + (long long)r * W1 + c4 * 4) = o;
}

// ---------------- semantic grouped 1x1 (groups=32, 4->4) + relu -------------
__global__ void s2_kernel(const float* __restrict__ x, const float* __restrict__ w,
                          const float* __restrict__ bias, float* __restrict__ y)
{
    const int i = blockIdx.x * blockDim.x + threadIdx.x;
    if (i >= BTK*W1) return;
    const int c = i & 127;
    const int r = i >> 7;
    const int base = (c >> 2) << 2;
    const float* xr = x + (long long)r*W1 + base;
    const float* wp = w + c*4;
    float acc = bias[c] + wp[0]*xr[0] + wp[1]*xr[1] + wp[2]*xr[2] + wp[3]*xr[3];
    y[i] = fmaxf(acc, 0.f);
}

// ---------------- fuse: relu(temporal + identity + max_k semantic) ----------
__global__ void fuse_kernel(const float* __restrict__ t3, const float* __restrict__ hin,
                            const float* __restrict__ s3, float* __restrict__ out)
{
    const int i = blockIdx.x * blockDim.x + threadIdx.x;
    if (i >= BT*HH) return;
    const int r = i >> 8;
    const int c = i & 255;
    const float* sr = s3 + ((long long)r*3)*HH + c;
    float m = fmaxf(fmaxf(sr[0], sr[HH]), sr[2*HH]);
    out[i] = fmaxf(t3[i] + hin[i] + m, 0.f);
}

// ---------------- host orchestration ----------------
static inline void gemm(const float* A, const float* W, const float* bias, float* C,
                        int M, int N, int Kd, bool relu, bool has_bias, int ldB = 0,
                        int batches = 1, long long sA = 0, long long sB = 0, long long sC = 0)
{
    if (ldB == 0) ldB = Kd;
    dim3 grid((N + 127) / 128, M / 128, batches);
    if (has_bias) {
        if (relu) {
            cudaFuncSetAttribute(mma_gemm_kernel<true, true>,
                                 cudaFuncAttributeMaxDynamicSharedMemorySize, SMEM_BYTES);
            mma_gemm_kernel<true, true><<<grid, 256, SMEM_BYTES>>>(A, W, bias, C, M, N, Kd, ldB, sA, sB, sC);
        } else {
            cudaFuncSetAttribute(mma_gemm_kernel<false, true>,
                                 cudaFuncAttributeMaxDynamicSharedMemorySize, SMEM_BYTES);
            mma_gemm_kernel<false, true><<<grid, 256, SMEM_BYTES>>>(A, W, bias, C, M, N, Kd, ldB, sA, sB, sC);
        }
    } else {
        if (relu) {
            cudaFuncSetAttribute(mma_gemm_kernel<true, false>,
                                 cudaFuncAttributeMaxDynamicSharedMemorySize, SMEM_BYTES);
            mma_gemm_kernel<true, false><<<grid, 256, SMEM_BYTES>>>(A, W, bias, C, M, N, Kd, ldB, sA, sB, sC);
        } else {
            cudaFuncSetAttribute(mma_gemm_kernel<false, false>,
                                 cudaFuncAttributeMaxDynamicSharedMemorySize, SMEM_BYTES);
            mma_gemm_kernel<false, false><<<grid, 256, SMEM_BYTES>>>(A, W, bias, C, M, N, Kd, ldB, sA, sB, sC);
        }
    }
}

extern "C" void kernel_launch(void* const* d_in, const int* in_sizes, int n_in,
                              void* d_out, int out_size)
{
    const float* x       = (const float*)d_in[0];
    const float* fc_in_w = (const float*)d_in[1];
    const float* fc_in_b = (const float*)d_in[2];
    const float* conv_w  = (const float*)d_in[3];
    const float* conv_b  = (const float*)d_in[4];
    const float* t1_w    = (const float*)d_in[5];
    const float* t1_b    = (const float*)d_in[6];
    const float* t2_w    = (const float*)d_in[7];
    const float* t2_b    = (const float*)d_in[8];
    const float* t3_w    = (const float*)d_in[9];
    const float* t3_b    = (const float*)d_in[10];
    const float* s1_w    = (const float*)d_in[11];
    const float* s1_b    = (const float*)d_in[12];
    const float* s2_w    = (const float*)d_in[13];
    const float* s2_b    = (const float*)d_in[14];
    const float* s3_w    = (const float*)d_in[15];
    const float* s3_b    = (const float*)d_in[16];
    const float* fc_w    = (const float*)d_in[17];
    const float* fc_b    = (const float*)d_in[18];
    float* out = (float*)d_out;

    float *hA, *hB, *t1, *t2, *t3, *xx, *pv, *u, *v, *s1, *s2, *s3;
    int *idx, *pi;
    cudaGetSymbolAddress((void**)&hA, g_hA);
    cudaGetSymbolAddress((void**)&hB, g_hB);
    cudaGetSymbolAddress((void**)&t1, g_t1);
    cudaGetSymbolAddress((void**)&t2, g_t2);
    cudaGetSymbolAddress((void**)&t3, g_t3);
    cudaGetSymbolAddress((void**)&xx, g_xx);
    cudaGetSymbolAddress((void**)&pv, g_pv);
    cudaGetSymbolAddress((void**)&pi, g_pi);
    cudaGetSymbolAddress((void**)&u,  g_u);
    cudaGetSymbolAddress((void**)&v,  g_v);
    cudaGetSymbolAddress((void**)&s1, g_s1);
    cudaGetSymbolAddress((void**)&s2, g_s2);
    cudaGetSymbolAddress((void**)&s3, g_s3);
    cudaGetSymbolAddress((void**)&idx, g_idx);

    // fc_in + relu: [BT,768] @ [256,768]^T -> hB
    gemm(x, fc_in_w, fc_in_b, hB, BT, HH, FEAT, true, true);
    // backbone grouped conv + relu: hB -> hA
    conv_backbone_kernel<<<BB * (TT/8), 256>>>(hB, conv_w, conv_b, hA);

    cudaFuncSetAttribute(inner_top3_kernel,
                         cudaFuncAttributeMaxDynamicSharedMemorySize, SMEM_BYTES);

    for (int l = 0; l < LL; l++) {
        const float* cur = (l == 0) ? hA : hB;
        float*       nxt = (l == 0) ? hB : hA;

        // ---- kNN graph (fused inner product + top3) ----
        rownorm_kernel<<<BT/8, 256>>>(cur, xx);
        {
            dim3 grid(8, 8, BB);
            inner_top3_kernel<<<grid, 256, SMEM_BYTES>>>(cur, xx, pv, pi);
        }
        top3_final_kernel<<<BT/256, 256>>>(pv, pi, idx);

        // ---- temporal branch ----
        gemm(cur, t1_w + l*W1*HH, t1_b + l*W1, t1, BT, W1, HH, true, true);
        conv_t2_kernel<<<(BT*W1 + 255)/256, 256>>>(t1, t2_w + l*W1*4*3, t2_b + l*W1, t2);
        gemm(t2, t3_w + l*HH*W1, t3_b + l*HH, t3, BT, HH, W1, false, true);

        // ---- semantic branch: s1 = relu(h@Wn^T [nbr] + h@Wc^T + b [ctr]) ----
        const float* s1wl = s1_w + l*W1*2*HH;
        gemm(cur, s1wl,      nullptr,      u, BT, W1, HH, false, false, 2*HH);
        gemm(cur, s1wl + HH, s1_b + l*W1,  v, BT, W1, HH, false, true,  2*HH);
        s1_fuse_kernel<<<BTK/8, 256>>>(u, v, idx, s1);
        s2_kernel<<<(BTK*W1 + 255)/256, 256>>>(s1, s2_w + l*W1*4, s2_b + l*W1, s2);
        gemm(s2, s3_w + l*HH*W1, s3_b + l*HH, s3, BTK, HH, W1, false, true);

        // ---- fuse ----
        fuse_kernel<<<(BT*HH + 255)/256, 256>>>(t3, cur, s3, nxt);
    }

    // final fc: [BT,256] @ [50,256]^T -> out
    gemm(hA, fc_w, fc_b, out, BT, CC, HH, false, true);
}